// round 11
// baseline (speedup 1.0000x reference)
#include <cuda_runtime.h>
#include <math.h>

#define BSZ 8192
#define SLN 49
#define FDIM 11
#define DEC_IN 138
#define NTHR 256

typedef unsigned long long ull;

__device__ __forceinline__ void fma2(ull& d, ull a, ull b) {
    asm("fma.rn.f32x2 %0, %1, %2, %0;" : "+l"(d) : "l"(a), "l"(b));
}
__device__ __forceinline__ ull pack2(float x, float y) {
    ull u; asm("mov.b64 %0, {%1, %2};" : "=l"(u) : "f"(x), "f"(y)); return u;
}
__device__ __forceinline__ float2 unpack2(ull u) {
    float2 v; asm("mov.b64 {%0, %1}, %2;" : "=f"(v.x), "=f"(v.y) : "l"(u)); return v;
}

// ---------------- device scratch ----------------
__device__ float g_sum[9];
__device__ float g_sumsq[9];
__device__ float g_mean[9];
__device__ float g_rstd[9];
__device__ float g_enc[BSZ * DEC_IN];
__device__ float g_h0[BSZ * 512];
__device__ float g_h1[BSZ * 256];

// ---------------- batch-norm statistics ----------------
__global__ void bn_zero_kernel() {
    if (threadIdx.x < 9) { g_sum[threadIdx.x] = 0.f; g_sumsq[threadIdx.x] = 0.f; }
}

__global__ void bn_acc_kernel(const float* __restrict__ in) {
    float ls[9], lq[9];
#pragma unroll
    for (int f = 0; f < 9; f++) { ls[f] = 0.f; lq[f] = 0.f; }
    int idx0 = blockIdx.x * blockDim.x + threadIdx.x;
    for (int r = idx0; r < BSZ * SLN; r += gridDim.x * blockDim.x) {
        const float* p = in + (size_t)r * FDIM;
#pragma unroll
        for (int f = 0; f < 9; f++) {
            float v = p[f < 8 ? f : 10];
            ls[f] += v; lq[f] += v * v;
        }
    }
#pragma unroll
    for (int f = 0; f < 9; f++) {
#pragma unroll
        for (int o = 16; o; o >>= 1) {
            ls[f] += __shfl_down_sync(0xffffffffu, ls[f], o);
            lq[f] += __shfl_down_sync(0xffffffffu, lq[f], o);
        }
    }
    if ((threadIdx.x & 31) == 0) {
#pragma unroll
        for (int f = 0; f < 9; f++) {
            atomicAdd(&g_sum[f], ls[f]);
            atomicAdd(&g_sumsq[f], lq[f]);
        }
    }
}

__global__ void bn_fin_kernel() {
    int f = threadIdx.x;
    if (f < 9) {
        float n = (float)(BSZ * SLN);
        float mu = g_sum[f] / n;
        float var = g_sumsq[f] / n - mu * mu;
        g_mean[f] = mu;
        g_rstd[f] = rsqrtf(var + 1e-5f);
    }
}

// ---------------- main per-element transformer kernel ----------------
struct MainParams {
    const float *in, *dists, *gamma, *beta;
    const float *xe_w1, *xe_b1, *xe_w2, *xe_b2;
    const float *ye_w1, *ye_b1, *ye_w2, *ye_b2;
    const float *learnable_y, *hidden_tokens;
    const float *Wq, *Wk, *Wv, *Wo, *Wq2, *Wk2, *Wv2, *Wo2;
};

#define TSTR 52
#define KSTR 52
#define SCSTR 52

struct __align__(16) Smem {
    float in[SLN][12];
    float csT[4][52];
    float snT[4][52];
    float bias[48];
    float ctxT[64][TSTR];
    float KT[64][KSTR];    // roped keys; reused as o-partial scratch after scores
    float V[48][64];
    float H[4][64];
    union {
        float tmpT[64][TSTR];
        struct {
            float sc[32][SCSTR];
            float q[4][64];
            float o[4][64];       // spacer for cross-attn partials
            float k2[4][64];
            float v2[4][64];
            float qc[64];
            float outv[64];
            float a2[32];
        } a;
    } u;
};

__global__ void __launch_bounds__(NTHR, 3) k_main(MainParams P, float* __restrict__ enc) {
    extern __shared__ char smem_raw[];
    Smem& s = *reinterpret_cast<Smem*>(smem_raw);
    const int tid = threadIdx.x;
    const int b = blockIdx.x;          // one element per CTA
    const int c = tid & 63;
    const int g = tid >> 6;            // group 0..3
    const int w = tid >> 5;            // warp 0..7
    const int lane = tid & 31;
    const int t0w = w * 6;             // 6-token chunk per warp

    // ---- phase 0 ----
    {
        const float* ib = P.in + (size_t)b * SLN * FDIM;
        for (int idx = tid; idx < SLN * FDIM; idx += NTHR) {
            int t = idx / FDIM, cc = idx % FDIM;
            float v = ib[idx];
            if (cc < 8 || cc == 10) {
                int f = (cc < 8) ? cc : 8;
                v = (v - g_mean[f]) * g_rstd[f] * P.gamma[f] + P.beta[f];
            }
            s.in[t][cc] = v;
        }
        for (int idx = tid; idx < 48; idx += NTHR)
            s.bias[idx] = -P.dists[(size_t)b * SLN + idx];
        for (int idx = tid; idx < SLN * 4; idx += NTHR) {
            int t = idx >> 2, j = idx & 3;
            float x = ib[t * FDIM + 8], y = ib[t * FDIM + 9];
            float ang = (j == 0) ? 10.f * x : (j == 1) ? 10.f * y : (j == 2) ? x : y;
            s.csT[j][t] = cosf(ang);
            s.snT[j][t] = sinf(ang);
        }
    }
    __syncthreads();

    // ---- x embed stage1 ----
    {
        float wv[8];
#pragma unroll
        for (int k = 0; k < 8; k++) wv[k] = P.xe_w1[k * 64 + c];
        float b1 = P.xe_b1[c];
        for (int t = g; t < SLN; t += 4) {
            float acc = b1;
#pragma unroll
            for (int k = 0; k < 8; k++) acc += s.in[t][k] * wv[k];
            s.u.tmpT[c][t] = acc - tanhf(acc);
        }
    }
    __syncthreads();
    // ---- x embed stage2: warp = 6-t chunk, lane handles cols lane & lane+32 ----
    {
        const float b2v0 = P.xe_b2[lane];
        const float b2v1 = P.xe_b2[lane + 32];
        ull acc[2][3];
#pragma unroll
        for (int p = 0; p < 3; p++) { acc[0][p] = pack2(b2v0, b2v0); acc[1][p] = pack2(b2v1, b2v1); }
        const float* Wc = P.xe_w2 + lane;
#pragma unroll 4
        for (int k = 0; k < 64; k++) {
            float w0 = Wc[k * 64], w1 = Wc[k * 64 + 32];
            ull wa = pack2(w0, w0), wb = pack2(w1, w1);
            const ull* act = reinterpret_cast<const ull*>(&s.u.tmpT[k][t0w]);
#pragma unroll
            for (int p = 0; p < 3; p++) {
                ull a2 = act[p];
                fma2(acc[0][p], a2, wa);
                fma2(acc[1][p], a2, wb);
            }
        }
#pragma unroll
        for (int half = 0; half < 2; half++) {
            float* dst = &s.ctxT[lane + 32 * half][t0w];
#pragma unroll
            for (int p = 0; p < 3; p++)
                *reinterpret_cast<float2*>(dst + 2 * p) = unpack2(acc[half][p]);
        }
        if (w == 0) {   // tail t=48
            float a0 = P.xe_b2[lane], a1 = P.xe_b2[lane + 32];
            for (int k = 0; k < 64; k++) {
                float tv = s.u.tmpT[k][48];
                a0 += tv * P.xe_w2[k * 64 + lane];
                a1 += tv * P.xe_w2[k * 64 + lane + 32];
            }
            s.ctxT[lane][48] = a0;
            s.ctxT[lane + 32][48] = a1;
        }
    }
    __syncthreads();

    const float scale = 0.35355339059327373f;  // 1/sqrt(8)

#pragma unroll 1
    for (int str = 0; str < 2; ++str) {
        if (str == 1) {
            {
                float w1v = P.ye_w1[c], b1 = P.ye_b1[c];
                for (int t = g; t < 48; t += 4) {
                    float acc = s.in[t][10] * w1v + b1;
                    s.u.tmpT[c][t] = acc - tanhf(acc);
                }
            }
            __syncthreads();
            {
                const float b2v0 = P.ye_b2[lane];
                const float b2v1 = P.ye_b2[lane + 32];
                ull acc[2][3];
#pragma unroll
                for (int p = 0; p < 3; p++) { acc[0][p] = pack2(b2v0, b2v0); acc[1][p] = pack2(b2v1, b2v1); }
                const float* Wc = P.ye_w2 + lane;
#pragma unroll 4
                for (int k = 0; k < 64; k++) {
                    float w0 = Wc[k * 64], w1 = Wc[k * 64 + 32];
                    ull wa = pack2(w0, w0), wb = pack2(w1, w1);
                    const ull* act = reinterpret_cast<const ull*>(&s.u.tmpT[k][t0w]);
#pragma unroll
                    for (int p = 0; p < 3; p++) {
                        ull a2 = act[p];
                        fma2(acc[0][p], a2, wa);
                        fma2(acc[1][p], a2, wb);
                    }
                }
#pragma unroll
                for (int half = 0; half < 2; half++) {
                    float* dst = &s.ctxT[lane + 32 * half][t0w];
#pragma unroll
                    for (int p = 0; p < 3; p++)
                        *reinterpret_cast<float2*>(dst + 2 * p) = unpack2(acc[half][p]);
                }
                if (w == 0) {
                    s.ctxT[lane][48] = P.learnable_y[lane];
                    s.ctxT[lane + 32][48] = P.learnable_y[lane + 32];
                }
            }
            __syncthreads();
        }

        s.H[g][c] = P.hidden_tokens[g * 64 + c];
        __syncthreads();

#pragma unroll 1
        for (int l = 0; l < 2; ++l) {
            const int woff = (l * 2 + str) * 4096;
            // ---- phase A: K+V projection (6 t per warp, cols lane & lane+32), fused rope ----
            {
                ull accK[2][3], accV[2][3];
#pragma unroll
                for (int p = 0; p < 3; p++) {
                    accK[0][p] = 0ull; accK[1][p] = 0ull;
                    accV[0][p] = 0ull; accV[1][p] = 0ull;
                }
                const float* WkB = P.Wk + woff + lane;
                const float* WvB = P.Wv + woff + lane;
#pragma unroll 4
                for (int k = 0; k < 64; k++) {
                    float wk0 = WkB[k * 64], wk1 = WkB[k * 64 + 32];
                    float wv0 = WvB[k * 64], wv1 = WvB[k * 64 + 32];
                    ull wka = pack2(wk0, wk0), wkb = pack2(wk1, wk1);
                    ull wva = pack2(wv0, wv0), wvb = pack2(wv1, wv1);
                    const ull* act = reinterpret_cast<const ull*>(&s.ctxT[k][t0w]);
#pragma unroll
                    for (int p = 0; p < 3; p++) {
                        ull a2 = act[p];
                        fma2(accK[0][p], a2, wka);
                        fma2(accK[1][p], a2, wkb);
                        fma2(accV[0][p], a2, wva);
                        fma2(accV[1][p], a2, wvb);
                    }
                }
                // V stores
#pragma unroll
                for (int half = 0; half < 2; half++)
#pragma unroll
                    for (int p = 0; p < 3; p++) {
                        float2 vv = unpack2(accV[half][p]);
                        s.V[t0w + 2 * p][lane + 32 * half] = vv.x;
                        s.V[t0w + 2 * p + 1][lane + 32 * half] = vv.y;
                    }
                // fused rope: partner lane = lane^1
                {
                    const int j = (lane >> 1) & 3;
                    const float sgn = (lane & 1) ? 1.f : -1.f;
                    const ull* cs8 = reinterpret_cast<const ull*>(&s.csT[j][t0w]);
                    const ull* sn8 = reinterpret_cast<const ull*>(&s.snT[j][t0w]);
                    ull cs2[3], sn2[3];
#pragma unroll
                    for (int p = 0; p < 3; p++) {
                        cs2[p] = cs8[p];
                        float2 sv = unpack2(sn8[p]);
                        sn2[p] = pack2(sgn * sv.x, sgn * sv.y);
                    }
#pragma unroll
                    for (int half = 0; half < 2; half++) {
                        float* dst = &s.KT[lane + 32 * half][t0w];
#pragma unroll
                        for (int p = 0; p < 3; p++) {
                            float2 mv = unpack2(accK[half][p]);
                            float ox = __shfl_xor_sync(0xffffffffu, mv.x, 1);
                            float oy = __shfl_xor_sync(0xffffffffu, mv.y, 1);
                            ull r = 0ull;
                            fma2(r, accK[half][p], cs2[p]);
                            fma2(r, pack2(ox, oy), sn2[p]);
                            *reinterpret_cast<float2*>(dst + 2 * p) = unpack2(r);
                        }
                    }
                }
            }
            // q projection (row = g)
            {
                float acc = 0.f;
#pragma unroll
                for (int kc = 0; kc < 64; kc += 8) {
                    float wv[8];
#pragma unroll
                    for (int j = 0; j < 8; j++) wv[j] = P.Wq[woff + (kc + j) * 64 + c];
                    const float4* h4 = reinterpret_cast<const float4*>(&s.H[g][kc]);
#pragma unroll
                    for (int q4 = 0; q4 < 2; q4++) {
                        float4 hv = h4[q4];
                        acc += hv.x * wv[4 * q4] + hv.y * wv[4 * q4 + 1] + hv.z * wv[4 * q4 + 2] + hv.w * wv[4 * q4 + 3];
                    }
                }
                s.u.a.q[g][c] = acc;
            }
            __syncthreads();
            // ---- phase B: fused scores + softmax ----
            {
                int r = tid >> 3, l8 = tid & 7;
                int h = r >> 2, i = r & 3;
                int t0 = l8 * 6;
                ull acc[3] = {0ull, 0ull, 0ull};
#pragma unroll
                for (int d = 0; d < 8; d++) {
                    float qv = s.u.a.q[i][h * 8 + d];
                    ull q2 = pack2(qv, qv);
                    const ull* kt = reinterpret_cast<const ull*>(&s.KT[h * 8 + d][t0]);
#pragma unroll
                    for (int p = 0; p < 3; p++) fma2(acc[p], kt[p], q2);
                }
                float sc[6];
#pragma unroll
                for (int p = 0; p < 3; p++) {
                    float2 v = unpack2(acc[p]);
                    float2 bb = *reinterpret_cast<const float2*>(&s.bias[t0 + 2 * p]);
                    sc[2 * p] = v.x * scale + bb.x;
                    sc[2 * p + 1] = v.y * scale + bb.y;
                }
                float m = sc[0];
#pragma unroll
                for (int ee = 1; ee < 6; ee++) m = fmaxf(m, sc[ee]);
#pragma unroll
                for (int o = 1; o < 8; o <<= 1) m = fmaxf(m, __shfl_xor_sync(0xffffffffu, m, o, 8));
                float sum = 0.f;
#pragma unroll
                for (int ee = 0; ee < 6; ee++) { sc[ee] = __expf(sc[ee] - m); sum += sc[ee]; }
#pragma unroll
                for (int o = 1; o < 8; o <<= 1) sum += __shfl_xor_sync(0xffffffffu, sum, o, 8);
                float inv = 1.f / sum;
#pragma unroll
                for (int p = 0; p < 3; p++)
                    *reinterpret_cast<float2*>(&s.u.a.sc[r][t0 + 2 * p]) =
                        make_float2(sc[2 * p] * inv, sc[2 * p + 1] * inv);
            }
            __syncthreads();
            // ---- phase C: o = a @ V partials into KT scratch ----
            {
                int p = tid & 31, g2 = tid >> 5;
                int gg = g2 & 3, thh = g2 >> 2;
                int r = (p >> 2) * 4 + gg;
                int tb = thh * 24;
                ull acc = 0ull;
#pragma unroll
                for (int q = 0; q < 6; q++) {
                    float4 av = reinterpret_cast<const float4*>(&s.u.a.sc[r][tb])[q];
                    float a0[4] = {av.x, av.y, av.z, av.w};
#pragma unroll
                    for (int cmp = 0; cmp < 4; cmp++) {
                        int t = tb + q * 4 + cmp;
                        float2 v0 = *reinterpret_cast<const float2*>(&s.V[t][2 * p]);
                        fma2(acc, pack2(v0.x, v0.y), pack2(a0[cmp], a0[cmp]));
                    }
                }
                float* ob = &s.KT[0][0];
                *reinterpret_cast<float2*>(&ob[thh * 256 + gg * 64 + 2 * p]) = unpack2(acc);
            }
            __syncthreads();
            // ---- phase D: H += (partial0+partial1) @ Wo ----
            {
                float acc = 0.f;
                const float* ob = &s.KT[0][0];
#pragma unroll
                for (int kc = 0; kc < 64; kc += 8) {
                    float wv[8];
#pragma unroll
                    for (int j = 0; j < 8; j++) wv[j] = P.Wo[woff + (kc + j) * 64 + c];
#pragma unroll
                    for (int q4 = 0; q4 < 2; q4++) {
                        float4 oa = *reinterpret_cast<const float4*>(&ob[g * 64 + kc + 4 * q4]);
                        float4 obp = *reinterpret_cast<const float4*>(&ob[256 + g * 64 + kc + 4 * q4]);
                        float ov0 = oa.x + obp.x, ov1 = oa.y + obp.y;
                        float ov2 = oa.z + obp.z, ov3 = oa.w + obp.w;
                        acc += ov0 * wv[4 * q4] + ov1 * wv[4 * q4 + 1] + ov2 * wv[4 * q4 + 2] + ov3 * wv[4 * q4 + 3];
                    }
                }
                s.H[g][c] += acc;
            }
            __syncthreads();
        }

        // ---- cross attention ----
        {
            const float* Wk2B = P.Wk2 + str * 4096 + c;
            const float* Wv2B = P.Wv2 + str * 4096 + c;
            float pk[4] = {}, pv[4] = {};
            const int k0 = g * 16;
            for (int kk = k0; kk < k0 + 16; kk += 2) {
                float wkA = Wk2B[kk * 64], wkB_ = Wk2B[(kk + 1) * 64];
                float wvA = Wv2B[kk * 64], wvB_ = Wv2B[(kk + 1) * 64];
#pragma unroll
                for (int i = 0; i < 4; i++) {
                    float2 hv = *reinterpret_cast<const float2*>(&s.H[i][kk]);
                    pk[i] += hv.x * wkA + hv.y * wkB_;
                    pv[i] += hv.x * wvA + hv.y * wvB_;
                }
            }
            float* part = &s.u.a.sc[0][0];
#pragma unroll
            for (int i = 0; i < 4; i++) {
                part[g * 256 + i * 64 + c] = pk[i];
                part[1024 + g * 256 + i * 64 + c] = pv[i];
            }
        }
        __syncthreads();
        {
            const float* part = &s.u.a.sc[0][0];
            float k2v = part[g * 64 + c] + part[256 + g * 64 + c] + part[512 + g * 64 + c] + part[768 + g * 64 + c];
            float v2v = part[1024 + g * 64 + c] + part[1280 + g * 64 + c] + part[1536 + g * 64 + c] + part[1792 + g * 64 + c];
            s.u.a.k2[g][c] = k2v;
            s.u.a.v2[g][c] = v2v;
            if (tid < 64) {
                int q = tid;
                float acc = 0.f;
                const float* W = P.Wq2 + str * 4096 + q;
#pragma unroll 8
                for (int k = 0; k < 64; k++) acc += s.ctxT[k][48] * W[k * 64];
                float other = __shfl_xor_sync(0xffffffffu, acc, 1);
                int jj = (q >> 1) & 3;
                float csv = s.csT[jj][48], snv = s.snT[jj][48];
                s.u.a.qc[q] = (q & 1) ? (snv * other + csv * acc) : (csv * acc - snv * other);
            }
        }
        __syncthreads();
        if (tid < 8) {
            int h = tid;
            float scv[4], m = -1e30f;
#pragma unroll
            for (int i = 0; i < 4; i++) {
                float acc = 0.f;
#pragma unroll
                for (int dd = 0; dd < 8; dd++) acc += s.u.a.qc[h * 8 + dd] * s.u.a.k2[i][h * 8 + dd];
                scv[i] = acc * scale;
                m = fmaxf(m, scv[i]);
            }
            float sum = 0.f;
#pragma unroll
            for (int i = 0; i < 4; i++) { scv[i] = __expf(scv[i] - m); sum += scv[i]; }
            float inv = 1.f / sum;
#pragma unroll
            for (int i = 0; i < 4; i++) s.u.a.a2[h * 4 + i] = scv[i] * inv;
        }
        __syncthreads();
        if (tid < 64) {
            int h = tid >> 3;
            float acc = 0.f;
#pragma unroll
            for (int i = 0; i < 4; i++) acc += s.u.a.a2[h * 4 + i] * s.u.a.v2[i][tid];
            s.u.a.outv[tid] = acc;
        }
        __syncthreads();
        if (tid < 64) {
            float acc = 0.f;
            const float* W = P.Wo2 + str * 4096 + tid;
#pragma unroll 8
            for (int k = 0; k < 64; k++) acc += s.u.a.outv[k] * W[k * 64];
            enc[(size_t)b * DEC_IN + str * 64 + tid] = acc;
        }
        __syncthreads();
    }

    if (tid < 10) enc[(size_t)b * DEC_IN + 128 + tid] = s.in[48][tid];
}

// ---------------- decoder GEMMs (f32x2 micro-kernel) ----------------
template <bool ACT>
__global__ void __launch_bounds__(256) gemm_kernel(const float* __restrict__ A, const float* __restrict__ B,
                                                   const float* __restrict__ bias, float* __restrict__ C,
                                                   int M, int N, int K) {
    const int BK = 16;
    __shared__ float As[BK][68];
    __shared__ float Bs[BK][64];
    int tx = threadIdx.x & 15, ty = threadIdx.x >> 4;
    int bm = blockIdx.x * 64, bn = blockIdx.y * 64;
    ull acc2[4][2] = {};
    for (int k0 = 0; k0 < K; k0 += BK) {
        for (int idx = threadIdx.x; idx < 64 * BK; idx += 256) {
            int r = idx >> 4, kk = idx & 15;
            As[kk][r] = (k0 + kk < K) ? A[(size_t)(bm + r) * K + k0 + kk] : 0.f;
        }
        for (int idx = threadIdx.x; idx < BK * 64; idx += 256) {
            int kk = idx >> 6, cc = idx & 63;
            Bs[kk][cc] = (k0 + kk < K) ? B[(size_t)(k0 + kk) * N + bn + cc] : 0.f;
        }
        __syncthreads();
#pragma unroll
        for (int kk = 0; kk < BK; kk++) {
            float4 av = *(const float4*)&As[kk][ty * 4];
            float4 bv = *(const float4*)&Bs[kk][tx * 4];
            ull b01 = pack2(bv.x, bv.y), b23 = pack2(bv.z, bv.w);
            float a[4] = {av.x, av.y, av.z, av.w};
#pragma unroll
            for (int i = 0; i < 4; i++) {
                ull a2 = pack2(a[i], a[i]);
                fma2(acc2[i][0], b01, a2);
                fma2(acc2[i][1], b23, a2);
            }
        }
        __syncthreads();
    }
#pragma unroll
    for (int i = 0; i < 4; i++) {
        int r = bm + ty * 4 + i;
        float2 v01 = unpack2(acc2[i][0]);
        float2 v23 = unpack2(acc2[i][1]);
        float vals[4] = {v01.x, v01.y, v23.x, v23.y};
#pragma unroll
        for (int j = 0; j < 4; j++) {
            int cc = bn + tx * 4 + j;
            float v = vals[j] + bias[cc];
            if (ACT) v -= tanhf(v);
            C[(size_t)r * N + cc] = v;
        }
    }
}

__global__ void __launch_bounds__(256) final_gemv(const float* __restrict__ H1, const float* __restrict__ w,
                                                  const float* __restrict__ b2, float* __restrict__ out) {
    int b = blockIdx.x * 8 + (threadIdx.x >> 5);
    int lane = threadIdx.x & 31;
    const float* row = H1 + (size_t)b * 256;
    float acc = 0.f;
#pragma unroll
    for (int k = lane; k < 256; k += 32) acc += row[k] * w[k];
#pragma unroll
    for (int o = 16; o; o >>= 1) acc += __shfl_down_sync(0xffffffffu, acc, o);
    if (lane == 0) out[b] = acc + b2[0];
}

// ---------------- launch ----------------
extern "C" void kernel_launch(void* const* d_in, const int* in_sizes, int n_in,
                              void* d_out, int out_size) {
    const float* in_t = (const float*)d_in[0];
    MainParams P;
    P.in = in_t;
    P.dists = (const float*)d_in[1];
    P.gamma = (const float*)d_in[3];  P.beta = (const float*)d_in[4];
    P.xe_w1 = (const float*)d_in[5];  P.xe_b1 = (const float*)d_in[6];
    P.xe_w2 = (const float*)d_in[7];  P.xe_b2 = (const float*)d_in[8];
    P.ye_w1 = (const float*)d_in[9];  P.ye_b1 = (const float*)d_in[10];
    P.ye_w2 = (const float*)d_in[11]; P.ye_b2 = (const float*)d_in[12];
    P.learnable_y = (const float*)d_in[13];
    P.hidden_tokens = (const float*)d_in[14];
    P.Wq = (const float*)d_in[15]; P.Wk = (const float*)d_in[16];
    P.Wv = (const float*)d_in[17]; P.Wo = (const float*)d_in[18];
    P.Wq2 = (const float*)d_in[19]; P.Wk2 = (const float*)d_in[20];
    P.Wv2 = (const float*)d_in[21]; P.Wo2 = (const float*)d_in[22];
    const float* dec_w0 = (const float*)d_in[23];
    const float* dec_b0 = (const float*)d_in[24];
    const float* dec_w1 = (const float*)d_in[25];
    const float* dec_b1 = (const float*)d_in[26];
    const float* dec_w2 = (const float*)d_in[27];
    const float* dec_b2 = (const float*)d_in[28];
    float* out = (float*)d_out;

    float *enc, *h0, *h1;
    cudaGetSymbolAddress((void**)&enc, g_enc);
    cudaGetSymbolAddress((void**)&h0, g_h0);
    cudaGetSymbolAddress((void**)&h1, g_h1);

    cudaFuncSetAttribute((const void*)k_main, cudaFuncAttributeMaxDynamicSharedMemorySize,
                         (int)sizeof(Smem));

    bn_zero_kernel<<<1, 32>>>();
    bn_acc_kernel<<<256, 256>>>(in_t);
    bn_fin_kernel<<<1, 32>>>();
    k_main<<<BSZ, NTHR, sizeof(Smem)>>>(P, enc);
    gemm_kernel<true><<<dim3(BSZ / 64, 512 / 64), 256>>>(enc, dec_w0, dec_b0, h0, BSZ, 512, DEC_IN);
    gemm_kernel<true><<<dim3(BSZ / 64, 256 / 64), 256>>>(h0, dec_w1, dec_b1, h1, BSZ, 256, 512);
    final_gemv<<<BSZ / 8, 256>>>(h1, dec_w2, dec_b2, out);
}

// round 12
// speedup vs baseline: 1.1799x; 1.1799x over previous
#include <cuda_runtime.h>
#include <math.h>

#define BSZ 8192
#define SLN 49
#define FDIM 11
#define DEC_IN 138
#define NTHR 256

typedef unsigned long long ull;

__device__ __forceinline__ void fma2(ull& d, ull a, ull b) {
    asm("fma.rn.f32x2 %0, %1, %2, %0;" : "+l"(d) : "l"(a), "l"(b));
}
__device__ __forceinline__ ull pack2(float x, float y) {
    ull u; asm("mov.b64 %0, {%1, %2};" : "=l"(u) : "f"(x), "f"(y)); return u;
}
__device__ __forceinline__ float2 unpack2(ull u) {
    float2 v; asm("mov.b64 {%0, %1}, %2;" : "=f"(v.x), "=f"(v.y) : "l"(u)); return v;
}

// ---------------- device scratch ----------------
__device__ float g_sum[9];
__device__ float g_sumsq[9];
__device__ float g_mean[9];
__device__ float g_rstd[9];
__device__ float g_enc[BSZ * DEC_IN];
__device__ float g_h0[BSZ * 512];
__device__ float g_h1[BSZ * 256];

// ---------------- batch-norm statistics ----------------
__global__ void bn_zero_kernel() {
    if (threadIdx.x < 9) { g_sum[threadIdx.x] = 0.f; g_sumsq[threadIdx.x] = 0.f; }
}

__global__ void bn_acc_kernel(const float* __restrict__ in) {
    float ls[9], lq[9];
#pragma unroll
    for (int f = 0; f < 9; f++) { ls[f] = 0.f; lq[f] = 0.f; }
    int idx0 = blockIdx.x * blockDim.x + threadIdx.x;
    for (int r = idx0; r < BSZ * SLN; r += gridDim.x * blockDim.x) {
        const float* p = in + (size_t)r * FDIM;
#pragma unroll
        for (int f = 0; f < 9; f++) {
            float v = p[f < 8 ? f : 10];
            ls[f] += v; lq[f] += v * v;
        }
    }
#pragma unroll
    for (int f = 0; f < 9; f++) {
#pragma unroll
        for (int o = 16; o; o >>= 1) {
            ls[f] += __shfl_down_sync(0xffffffffu, ls[f], o);
            lq[f] += __shfl_down_sync(0xffffffffu, lq[f], o);
        }
    }
    if ((threadIdx.x & 31) == 0) {
#pragma unroll
        for (int f = 0; f < 9; f++) {
            atomicAdd(&g_sum[f], ls[f]);
            atomicAdd(&g_sumsq[f], lq[f]);
        }
    }
}

__global__ void bn_fin_kernel() {
    int f = threadIdx.x;
    if (f < 9) {
        float n = (float)(BSZ * SLN);
        float mu = g_sum[f] / n;
        float var = g_sumsq[f] / n - mu * mu;
        g_mean[f] = mu;
        g_rstd[f] = rsqrtf(var + 1e-5f);
    }
}

// ---------------- main per-element transformer kernel ----------------
struct MainParams {
    const float *in, *dists, *gamma, *beta;
    const float *xe_w1, *xe_b1, *xe_w2, *xe_b2;
    const float *ye_w1, *ye_b1, *ye_w2, *ye_b2;
    const float *learnable_y, *hidden_tokens;
    const float *Wq, *Wk, *Wv, *Wo, *Wq2, *Wk2, *Wv2, *Wo2;
};

#define TSTR 52
#define KSTR 52
#define SCSTR 52

struct __align__(16) PerElem {
    float in[SLN][12];
    float csT[4][52];
    float snT[4][52];
    float bias[48];
    float ctxT[64][TSTR];
    float KT[64][KSTR];    // roped keys; reused as o-partial scratch after scores
    float V[48][64];
    float H[4][64];
    union {
        float tmpT[64][TSTR];
        struct {
            float sc[32][SCSTR];
            float q[4][64];
            float o[4][64];       // spacer for cross-attn partials
            float k2[4][64];
            float v2[4][64];
            float qc[64];
            float outv[64];
            float a2[32];
        } a;
    } u;
};

struct __align__(16) Smem { PerElem el[2]; };

__global__ void __launch_bounds__(NTHR, 2) k_main(MainParams P, float* __restrict__ enc) {
    extern __shared__ char smem_raw[];
    Smem& s = *reinterpret_cast<Smem*>(smem_raw);
    const int tid = threadIdx.x;
    const int b = blockIdx.x;          // elements 2b, 2b+1
    const int c = tid & 63;
    const int g = tid >> 6;            // group 0..3 (legacy mapping phases)
    const int w = tid >> 5;            // warp 0..7
    const int lane = tid & 31;
    const int ew = w & 1;              // element this warp serves
    const int th = w >> 1;             // t-chunk 0..3 (12 t each)
    const int t0w = th * 12;

    // ---- phase 0 ----
#pragma unroll 1
    for (int e = 0; e < 2; e++) {
        PerElem& E = s.el[e];
        const float* ib = P.in + (size_t)(2 * b + e) * SLN * FDIM;
        for (int idx = tid; idx < SLN * FDIM; idx += NTHR) {
            int t = idx / FDIM, cc = idx % FDIM;
            float v = ib[idx];
            if (cc < 8 || cc == 10) {
                int f = (cc < 8) ? cc : 8;
                v = (v - g_mean[f]) * g_rstd[f] * P.gamma[f] + P.beta[f];
            }
            E.in[t][cc] = v;
        }
        for (int idx = tid; idx < 48; idx += NTHR)
            E.bias[idx] = -P.dists[(size_t)(2 * b + e) * SLN + idx];
        for (int idx = tid; idx < SLN * 4; idx += NTHR) {
            int t = idx >> 2, j = idx & 3;
            float x = ib[t * FDIM + 8], y = ib[t * FDIM + 9];
            float ang = (j == 0) ? 10.f * x : (j == 1) ? 10.f * y : (j == 2) ? x : y;
            E.csT[j][t] = cosf(ang);
            E.snT[j][t] = sinf(ang);
        }
    }
    __syncthreads();

    // ---- x embed stage1 (legacy mapping) ----
    {
        float wv[8];
#pragma unroll
        for (int k = 0; k < 8; k++) wv[k] = __ldg(&P.xe_w1[k * 64 + c]);
        float b1 = P.xe_b1[c];
#pragma unroll
        for (int e = 0; e < 2; e++) {
            PerElem& E = s.el[e];
            for (int t = g; t < SLN; t += 4) {
                float acc = b1;
#pragma unroll
                for (int k = 0; k < 8; k++) acc += E.in[t][k] * wv[k];
                E.u.tmpT[c][t] = acc - tanhf(acc);
            }
        }
    }
    __syncthreads();
    // ---- x embed stage2: warp=(elem,t-chunk), lane handles c=lane & lane+32 ----
    {
        PerElem& E = s.el[ew];
        const float b2v0 = P.xe_b2[lane];
        const float b2v1 = P.xe_b2[lane + 32];
        ull acc[2][6];
#pragma unroll
        for (int p = 0; p < 6; p++) { acc[0][p] = pack2(b2v0, b2v0); acc[1][p] = pack2(b2v1, b2v1); }
        const float* Wc = P.xe_w2 + lane;
#pragma unroll 8
        for (int k = 0; k < 64; k++) {
            float w0 = __ldg(&Wc[k * 64]), w1 = __ldg(&Wc[k * 64 + 32]);
            ull wa = pack2(w0, w0), wb = pack2(w1, w1);
            const ulonglong2* act = reinterpret_cast<const ulonglong2*>(&E.u.tmpT[k][t0w]);
#pragma unroll
            for (int p = 0; p < 3; p++) {
                ulonglong2 a4 = act[p];
                fma2(acc[0][2 * p], a4.x, wa);
                fma2(acc[0][2 * p + 1], a4.y, wa);
                fma2(acc[1][2 * p], a4.x, wb);
                fma2(acc[1][2 * p + 1], a4.y, wb);
            }
        }
#pragma unroll
        for (int half = 0; half < 2; half++) {
            float2 r0 = unpack2(acc[half][0]), r1 = unpack2(acc[half][1]);
            float2 r2 = unpack2(acc[half][2]), r3 = unpack2(acc[half][3]);
            float2 r4 = unpack2(acc[half][4]), r5 = unpack2(acc[half][5]);
            float* dst = &E.ctxT[lane + 32 * half][t0w];
            *reinterpret_cast<float4*>(dst) = make_float4(r0.x, r0.y, r1.x, r1.y);
            *reinterpret_cast<float4*>(dst + 4) = make_float4(r2.x, r2.y, r3.x, r3.y);
            *reinterpret_cast<float4*>(dst + 8) = make_float4(r4.x, r4.y, r5.x, r5.y);
        }
        if (w < 2) {   // tail t=48
            PerElem& Et = s.el[w];
            float a0 = P.xe_b2[lane], a1 = P.xe_b2[lane + 32];
            const float* W = P.xe_w2;
            for (int k = 0; k < 64; k++) {
                float tv = Et.u.tmpT[k][48];
                a0 += tv * __ldg(&W[k * 64 + lane]);
                a1 += tv * __ldg(&W[k * 64 + lane + 32]);
            }
            Et.ctxT[lane][48] = a0;
            Et.ctxT[lane + 32][48] = a1;
        }
    }
    __syncthreads();

    const float scale = 0.35355339059327373f;  // 1/sqrt(8)

#pragma unroll 1
    for (int str = 0; str < 2; ++str) {
        if (str == 1) {
            {
                float w1v = P.ye_w1[c], b1 = P.ye_b1[c];
#pragma unroll
                for (int e = 0; e < 2; e++) {
                    PerElem& E = s.el[e];
                    for (int t = g; t < 48; t += 4) {
                        float acc = E.in[t][10] * w1v + b1;
                        E.u.tmpT[c][t] = acc - tanhf(acc);
                    }
                }
            }
            __syncthreads();
            {
                PerElem& E = s.el[ew];
                const float b2v0 = P.ye_b2[lane];
                const float b2v1 = P.ye_b2[lane + 32];
                ull acc[2][6];
#pragma unroll
                for (int p = 0; p < 6; p++) { acc[0][p] = pack2(b2v0, b2v0); acc[1][p] = pack2(b2v1, b2v1); }
                const float* Wc = P.ye_w2 + lane;
#pragma unroll 8
                for (int k = 0; k < 64; k++) {
                    float w0 = __ldg(&Wc[k * 64]), w1 = __ldg(&Wc[k * 64 + 32]);
                    ull wa = pack2(w0, w0), wb = pack2(w1, w1);
                    const ulonglong2* act = reinterpret_cast<const ulonglong2*>(&E.u.tmpT[k][t0w]);
#pragma unroll
                    for (int p = 0; p < 3; p++) {
                        ulonglong2 a4 = act[p];
                        fma2(acc[0][2 * p], a4.x, wa);
                        fma2(acc[0][2 * p + 1], a4.y, wa);
                        fma2(acc[1][2 * p], a4.x, wb);
                        fma2(acc[1][2 * p + 1], a4.y, wb);
                    }
                }
#pragma unroll
                for (int half = 0; half < 2; half++) {
                    float2 r0 = unpack2(acc[half][0]), r1 = unpack2(acc[half][1]);
                    float2 r2 = unpack2(acc[half][2]), r3 = unpack2(acc[half][3]);
                    float2 r4 = unpack2(acc[half][4]), r5 = unpack2(acc[half][5]);
                    float* dst = &E.ctxT[lane + 32 * half][t0w];
                    *reinterpret_cast<float4*>(dst) = make_float4(r0.x, r0.y, r1.x, r1.y);
                    *reinterpret_cast<float4*>(dst + 4) = make_float4(r2.x, r2.y, r3.x, r3.y);
                    *reinterpret_cast<float4*>(dst + 8) = make_float4(r4.x, r4.y, r5.x, r5.y);
                }
                if (w < 2) {
                    s.el[w].ctxT[lane][48] = P.learnable_y[lane];
                    s.el[w].ctxT[lane + 32][48] = P.learnable_y[lane + 32];
                }
            }
            __syncthreads();
        }

#pragma unroll
        for (int e = 0; e < 2; e++) s.el[e].H[g][c] = P.hidden_tokens[g * 64 + c];
        __syncthreads();

#pragma unroll 1
        for (int l = 0; l < 2; ++l) {
            const int woff = (l * 2 + str) * 4096;
            // ---- phase A: K+V projection, warp=(elem,t-chunk), lane = c & c+32, fused rope ----
            {
                PerElem& E = s.el[ew];
                ull accK[2][6], accV[2][6];
#pragma unroll
                for (int p = 0; p < 6; p++) {
                    accK[0][p] = 0ull; accK[1][p] = 0ull;
                    accV[0][p] = 0ull; accV[1][p] = 0ull;
                }
                const float* WkB = P.Wk + woff + lane;
                const float* WvB = P.Wv + woff + lane;
#pragma unroll 8
                for (int k = 0; k < 64; k++) {
                    float wk0 = __ldg(&WkB[k * 64]), wk1 = __ldg(&WkB[k * 64 + 32]);
                    float wv0 = __ldg(&WvB[k * 64]), wv1 = __ldg(&WvB[k * 64 + 32]);
                    ull wka = pack2(wk0, wk0), wkb = pack2(wk1, wk1);
                    ull wva = pack2(wv0, wv0), wvb = pack2(wv1, wv1);
                    const ulonglong2* act = reinterpret_cast<const ulonglong2*>(&E.ctxT[k][t0w]);
#pragma unroll
                    for (int p = 0; p < 3; p++) {
                        ulonglong2 a4 = act[p];
                        fma2(accK[0][2 * p], a4.x, wka);
                        fma2(accK[0][2 * p + 1], a4.y, wka);
                        fma2(accK[1][2 * p], a4.x, wkb);
                        fma2(accK[1][2 * p + 1], a4.y, wkb);
                        fma2(accV[0][2 * p], a4.x, wva);
                        fma2(accV[0][2 * p + 1], a4.y, wva);
                        fma2(accV[1][2 * p], a4.x, wvb);
                        fma2(accV[1][2 * p + 1], a4.y, wvb);
                    }
                }
                // V stores
#pragma unroll
                for (int half = 0; half < 2; half++)
#pragma unroll
                    for (int p = 0; p < 6; p++) {
                        float2 vv = unpack2(accV[half][p]);
                        E.V[t0w + 2 * p][lane + 32 * half] = vv.x;
                        E.V[t0w + 2 * p + 1][lane + 32 * half] = vv.y;
                    }
                // fused rope: partner lane = lane^1
                {
                    const int j = (lane >> 1) & 3;
                    const float sgn = (lane & 1) ? 1.f : -1.f;
                    float4 csA = *reinterpret_cast<const float4*>(&E.csT[j][t0w]);
                    float4 csB = *reinterpret_cast<const float4*>(&E.csT[j][t0w + 4]);
                    float4 csC = *reinterpret_cast<const float4*>(&E.csT[j][t0w + 8]);
                    float4 snA = *reinterpret_cast<const float4*>(&E.snT[j][t0w]);
                    float4 snB = *reinterpret_cast<const float4*>(&E.snT[j][t0w + 4]);
                    float4 snC = *reinterpret_cast<const float4*>(&E.snT[j][t0w + 8]);
                    ull cs2[6] = {pack2(csA.x, csA.y), pack2(csA.z, csA.w),
                                  pack2(csB.x, csB.y), pack2(csB.z, csB.w),
                                  pack2(csC.x, csC.y), pack2(csC.z, csC.w)};
                    ull sn2[6] = {pack2(sgn * snA.x, sgn * snA.y), pack2(sgn * snA.z, sgn * snA.w),
                                  pack2(sgn * snB.x, sgn * snB.y), pack2(sgn * snB.z, sgn * snB.w),
                                  pack2(sgn * snC.x, sgn * snC.y), pack2(sgn * snC.z, sgn * snC.w)};
#pragma unroll
                    for (int half = 0; half < 2; half++) {
                        float2 rr[6];
#pragma unroll
                        for (int p = 0; p < 6; p++) {
                            float2 mv = unpack2(accK[half][p]);
                            float ox = __shfl_xor_sync(0xffffffffu, mv.x, 1);
                            float oy = __shfl_xor_sync(0xffffffffu, mv.y, 1);
                            ull r = 0ull;
                            fma2(r, accK[half][p], cs2[p]);
                            fma2(r, pack2(ox, oy), sn2[p]);
                            rr[p] = unpack2(r);
                        }
                        float* dst = &E.KT[lane + 32 * half][t0w];
                        *reinterpret_cast<float4*>(dst) = make_float4(rr[0].x, rr[0].y, rr[1].x, rr[1].y);
                        *reinterpret_cast<float4*>(dst + 4) = make_float4(rr[2].x, rr[2].y, rr[3].x, rr[3].y);
                        *reinterpret_cast<float4*>(dst + 8) = make_float4(rr[4].x, rr[4].y, rr[5].x, rr[5].y);
                    }
                }
            }
            // q projection (legacy mapping, row = g)
            {
                float acc[2] = {0.f, 0.f};
#pragma unroll
                for (int kc = 0; kc < 64; kc += 8) {
                    float wv[8];
#pragma unroll
                    for (int j = 0; j < 8; j++) wv[j] = __ldg(&P.Wq[woff + (kc + j) * 64 + c]);
#pragma unroll
                    for (int e = 0; e < 2; e++) {
                        const float4* h4 = reinterpret_cast<const float4*>(&s.el[e].H[g][kc]);
#pragma unroll
                        for (int q4 = 0; q4 < 2; q4++) {
                            float4 hv = h4[q4];
                            acc[e] += hv.x * wv[4 * q4] + hv.y * wv[4 * q4 + 1] + hv.z * wv[4 * q4 + 2] + hv.w * wv[4 * q4 + 3];
                        }
                    }
                }
                s.el[0].u.a.q[g][c] = acc[0];
                s.el[1].u.a.q[g][c] = acc[1];
            }
            __syncthreads();
            // ---- phase B: fused scores + softmax ----
            {
                int r = tid >> 3, l8 = tid & 7;
                int h = r >> 2, i = r & 3;
                int t0 = l8 * 6;
                ull acc[2][3] = {{0ull, 0ull, 0ull}, {0ull, 0ull, 0ull}};
#pragma unroll
                for (int d = 0; d < 8; d++) {
#pragma unroll
                    for (int e = 0; e < 2; e++) {
                        PerElem& E = s.el[e];
                        float qv = E.u.a.q[i][h * 8 + d];
                        ull q2 = pack2(qv, qv);
                        const float2* kt = reinterpret_cast<const float2*>(&E.KT[h * 8 + d][t0]);
#pragma unroll
                        for (int p = 0; p < 3; p++) {
                            float2 kv = kt[p];
                            fma2(acc[e][p], pack2(kv.x, kv.y), q2);
                        }
                    }
                }
#pragma unroll
                for (int e = 0; e < 2; e++) {
                    PerElem& E = s.el[e];
                    float sc[6];
#pragma unroll
                    for (int p = 0; p < 3; p++) {
                        float2 v = unpack2(acc[e][p]);
                        float2 bb = *reinterpret_cast<const float2*>(&E.bias[t0 + 2 * p]);
                        sc[2 * p] = v.x * scale + bb.x;
                        sc[2 * p + 1] = v.y * scale + bb.y;
                    }
                    float m = sc[0];
#pragma unroll
                    for (int ee = 1; ee < 6; ee++) m = fmaxf(m, sc[ee]);
#pragma unroll
                    for (int o = 1; o < 8; o <<= 1) m = fmaxf(m, __shfl_xor_sync(0xffffffffu, m, o, 8));
                    float sum = 0.f;
#pragma unroll
                    for (int ee = 0; ee < 6; ee++) { sc[ee] = __expf(sc[ee] - m); sum += sc[ee]; }
#pragma unroll
                    for (int o = 1; o < 8; o <<= 1) sum += __shfl_xor_sync(0xffffffffu, sum, o, 8);
                    float inv = 1.f / sum;
#pragma unroll
                    for (int p = 0; p < 3; p++)
                        *reinterpret_cast<float2*>(&E.u.a.sc[r][t0 + 2 * p]) =
                            make_float2(sc[2 * p] * inv, sc[2 * p + 1] * inv);
                }
            }
            __syncthreads();
            // ---- phase C: o = a @ V partials into KT scratch ----
            {
                int p = tid & 31, g2 = tid >> 5;
                int gg = g2 & 3, thh = g2 >> 2;
                int r = (p >> 2) * 4 + gg;
                int tb = thh * 24;
                ull acc[2] = {0ull, 0ull};
#pragma unroll
                for (int q = 0; q < 6; q++) {
                    float4 av0 = reinterpret_cast<const float4*>(&s.el[0].u.a.sc[r][tb])[q];
                    float4 av1 = reinterpret_cast<const float4*>(&s.el[1].u.a.sc[r][tb])[q];
                    float a0[4] = {av0.x, av0.y, av0.z, av0.w};
                    float a1[4] = {av1.x, av1.y, av1.z, av1.w};
#pragma unroll
                    for (int cmp = 0; cmp < 4; cmp++) {
                        int t = tb + q * 4 + cmp;
                        float2 v0 = *reinterpret_cast<const float2*>(&s.el[0].V[t][2 * p]);
                        float2 v1 = *reinterpret_cast<const float2*>(&s.el[1].V[t][2 * p]);
                        fma2(acc[0], pack2(v0.x, v0.y), pack2(a0[cmp], a0[cmp]));
                        fma2(acc[1], pack2(v1.x, v1.y), pack2(a1[cmp], a1[cmp]));
                    }
                }
                float* ob0 = &s.el[0].KT[0][0];
                float* ob1 = &s.el[1].KT[0][0];
                *reinterpret_cast<float2*>(&ob0[thh * 256 + gg * 64 + 2 * p]) = unpack2(acc[0]);
                *reinterpret_cast<float2*>(&ob1[thh * 256 + gg * 64 + 2 * p]) = unpack2(acc[1]);
            }
            __syncthreads();
            // ---- phase D: H += (partial0+partial1) @ Wo ----
            {
                float acc[2] = {0.f, 0.f};
#pragma unroll
                for (int kc = 0; kc < 64; kc += 8) {
                    float wv[8];
#pragma unroll
                    for (int j = 0; j < 8; j++) wv[j] = __ldg(&P.Wo[woff + (kc + j) * 64 + c]);
#pragma unroll
                    for (int e = 0; e < 2; e++) {
                        const float* ob = &s.el[e].KT[0][0];
#pragma unroll
                        for (int q4 = 0; q4 < 2; q4++) {
                            float4 oa = *reinterpret_cast<const float4*>(&ob[g * 64 + kc + 4 * q4]);
                            float4 obp = *reinterpret_cast<const float4*>(&ob[256 + g * 64 + kc + 4 * q4]);
                            float ov0 = oa.x + obp.x, ov1 = oa.y + obp.y;
                            float ov2 = oa.z + obp.z, ov3 = oa.w + obp.w;
                            acc[e] += ov0 * wv[4 * q4] + ov1 * wv[4 * q4 + 1] + ov2 * wv[4 * q4 + 2] + ov3 * wv[4 * q4 + 3];
                        }
                    }
                }
                s.el[0].H[g][c] += acc[0];
                s.el[1].H[g][c] += acc[1];
            }
            __syncthreads();
        }

        // ---- cross attention ----
        {
            const float* Wk2B = P.Wk2 + str * 4096 + c;
            const float* Wv2B = P.Wv2 + str * 4096 + c;
            float pk[2][4] = {}, pv[2][4] = {};
            const int k0 = g * 16;
            for (int kk = k0; kk < k0 + 16; kk += 2) {
                float wkA = __ldg(&Wk2B[kk * 64]), wkB_ = __ldg(&Wk2B[(kk + 1) * 64]);
                float wvA = __ldg(&Wv2B[kk * 64]), wvB_ = __ldg(&Wv2B[(kk + 1) * 64]);
#pragma unroll
                for (int e = 0; e < 2; e++)
#pragma unroll
                    for (int i = 0; i < 4; i++) {
                        float2 hv = *reinterpret_cast<const float2*>(&s.el[e].H[i][kk]);
                        pk[e][i] += hv.x * wkA + hv.y * wkB_;
                        pv[e][i] += hv.x * wvA + hv.y * wvB_;
                    }
            }
#pragma unroll
            for (int e = 0; e < 2; e++) {
                float* part = &s.el[e].u.a.sc[0][0];
#pragma unroll
                for (int i = 0; i < 4; i++) {
                    part[g * 256 + i * 64 + c] = pk[e][i];
                    part[1024 + g * 256 + i * 64 + c] = pv[e][i];
                }
            }
        }
        __syncthreads();
        {
#pragma unroll
            for (int e = 0; e < 2; e++) {
                const float* part = &s.el[e].u.a.sc[0][0];
                float k2v = part[g * 64 + c] + part[256 + g * 64 + c] + part[512 + g * 64 + c] + part[768 + g * 64 + c];
                float v2v = part[1024 + g * 64 + c] + part[1280 + g * 64 + c] + part[1536 + g * 64 + c] + part[1792 + g * 64 + c];
                s.el[e].u.a.k2[g][c] = k2v;
                s.el[e].u.a.v2[g][c] = v2v;
            }
            if (tid < 128) {
                int e = tid >> 6, q = tid & 63;
                PerElem& E = s.el[e];
                float acc = 0.f;
                const float* W = P.Wq2 + str * 4096 + q;
#pragma unroll 8
                for (int k = 0; k < 64; k++) acc += E.ctxT[k][48] * __ldg(&W[k * 64]);
                float other = __shfl_xor_sync(0xffffffffu, acc, 1);
                int jj = (q >> 1) & 3;
                float csv = E.csT[jj][48], snv = E.snT[jj][48];
                E.u.a.qc[q] = (q & 1) ? (snv * other + csv * acc) : (csv * acc - snv * other);
            }
        }
        __syncthreads();
        if (tid < 16) {
            int e = tid >> 3, h = tid & 7;
            PerElem& E = s.el[e];
            float scv[4], m = -1e30f;
#pragma unroll
            for (int i = 0; i < 4; i++) {
                float acc = 0.f;
#pragma unroll
                for (int dd = 0; dd < 8; dd++) acc += E.u.a.qc[h * 8 + dd] * E.u.a.k2[i][h * 8 + dd];
                scv[i] = acc * scale;
                m = fmaxf(m, scv[i]);
            }
            float sum = 0.f;
#pragma unroll
            for (int i = 0; i < 4; i++) { scv[i] = __expf(scv[i] - m); sum += scv[i]; }
            float inv = 1.f / sum;
#pragma unroll
            for (int i = 0; i < 4; i++) E.u.a.a2[h * 4 + i] = scv[i] * inv;
        }
        __syncthreads();
        if (tid < 128) {
            int e = tid >> 6, q = tid & 63;
            PerElem& E = s.el[e];
            int h = q >> 3;
            float acc = 0.f;
#pragma unroll
            for (int i = 0; i < 4; i++) acc += E.u.a.a2[h * 4 + i] * E.u.a.v2[i][q];
            E.u.a.outv[q] = acc;
        }
        __syncthreads();
        if (tid < 128) {
            int e = tid >> 6, q = tid & 63;
            PerElem& E = s.el[e];
            float acc = 0.f;
            const float* W = P.Wo2 + str * 4096 + q;
#pragma unroll 8
            for (int k = 0; k < 64; k++) acc += E.u.a.outv[k] * __ldg(&W[k * 64]);
            enc[(size_t)(2 * b + e) * DEC_IN + str * 64 + q] = acc;
        }
        __syncthreads();
    }

    if (tid < 10) {
        enc[(size_t)(2 * b) * DEC_IN + 128 + tid] = s.el[0].in[48][tid];
        enc[(size_t)(2 * b + 1) * DEC_IN + 128 + tid] = s.el[1].in[48][tid];
    }
}

// ---------------- decoder GEMMs (f32x2 micro-kernel) ----------------
template <bool ACT>
__global__ void __launch_bounds__(256) gemm_kernel(const float* __restrict__ A, const float* __restrict__ B,
                                                   const float* __restrict__ bias, float* __restrict__ C,
                                                   int M, int N, int K) {
    const int BK = 16;
    __shared__ float As[BK][68];
    __shared__ float Bs[BK][64];
    int tx = threadIdx.x & 15, ty = threadIdx.x >> 4;
    int bm = blockIdx.x * 64, bn = blockIdx.y * 64;
    ull acc2[4][2] = {};
    for (int k0 = 0; k0 < K; k0 += BK) {
        for (int idx = threadIdx.x; idx < 64 * BK; idx += 256) {
            int r = idx >> 4, kk = idx & 15;
            As[kk][r] = (k0 + kk < K) ? A[(size_t)(bm + r) * K + k0 + kk] : 0.f;
        }
        for (int idx = threadIdx.x; idx < BK * 64; idx += 256) {
            int kk = idx >> 6, cc = idx & 63;
            Bs[kk][cc] = (k0 + kk < K) ? B[(size_t)(k0 + kk) * N + bn + cc] : 0.f;
        }
        __syncthreads();
#pragma unroll
        for (int kk = 0; kk < BK; kk++) {
            float4 av = *(const float4*)&As[kk][ty * 4];
            float4 bv = *(const float4*)&Bs[kk][tx * 4];
            ull b01 = pack2(bv.x, bv.y), b23 = pack2(bv.z, bv.w);
            float a[4] = {av.x, av.y, av.z, av.w};
#pragma unroll
            for (int i = 0; i < 4; i++) {
                ull a2 = pack2(a[i], a[i]);
                fma2(acc2[i][0], b01, a2);
                fma2(acc2[i][1], b23, a2);
            }
        }
        __syncthreads();
    }
#pragma unroll
    for (int i = 0; i < 4; i++) {
        int r = bm + ty * 4 + i;
        float2 v01 = unpack2(acc2[i][0]);
        float2 v23 = unpack2(acc2[i][1]);
        float vals[4] = {v01.x, v01.y, v23.x, v23.y};
#pragma unroll
        for (int j = 0; j < 4; j++) {
            int cc = bn + tx * 4 + j;
            float v = vals[j] + bias[cc];
            if (ACT) v -= tanhf(v);
            C[(size_t)r * N + cc] = v;
        }
    }
}

__global__ void __launch_bounds__(256) final_gemv(const float* __restrict__ H1, const float* __restrict__ w,
                                                  const float* __restrict__ b2, float* __restrict__ out) {
    int b = blockIdx.x * 8 + (threadIdx.x >> 5);
    int lane = threadIdx.x & 31;
    const float* row = H1 + (size_t)b * 256;
    float acc = 0.f;
#pragma unroll
    for (int k = lane; k < 256; k += 32) acc += row[k] * w[k];
#pragma unroll
    for (int o = 16; o; o >>= 1) acc += __shfl_down_sync(0xffffffffu, acc, o);
    if (lane == 0) out[b] = acc + b2[0];
}

// ---------------- launch ----------------
extern "C" void kernel_launch(void* const* d_in, const int* in_sizes, int n_in,
                              void* d_out, int out_size) {
    const float* in_t = (const float*)d_in[0];
    MainParams P;
    P.in = in_t;
    P.dists = (const float*)d_in[1];
    P.gamma = (const float*)d_in[3];  P.beta = (const float*)d_in[4];
    P.xe_w1 = (const float*)d_in[5];  P.xe_b1 = (const float*)d_in[6];
    P.xe_w2 = (const float*)d_in[7];  P.xe_b2 = (const float*)d_in[8];
    P.ye_w1 = (const float*)d_in[9];  P.ye_b1 = (const float*)d_in[10];
    P.ye_w2 = (const float*)d_in[11]; P.ye_b2 = (const float*)d_in[12];
    P.learnable_y = (const float*)d_in[13];
    P.hidden_tokens = (const float*)d_in[14];
    P.Wq = (const float*)d_in[15]; P.Wk = (const float*)d_in[16];
    P.Wv = (const float*)d_in[17]; P.Wo = (const float*)d_in[18];
    P.Wq2 = (const float*)d_in[19]; P.Wk2 = (const float*)d_in[20];
    P.Wv2 = (const float*)d_in[21]; P.Wo2 = (const float*)d_in[22];
    const float* dec_w0 = (const float*)d_in[23];
    const float* dec_b0 = (const float*)d_in[24];
    const float* dec_w1 = (const float*)d_in[25];
    const float* dec_b1 = (const float*)d_in[26];
    const float* dec_w2 = (const float*)d_in[27];
    const float* dec_b2 = (const float*)d_in[28];
    float* out = (float*)d_out;

    float *enc, *h0, *h1;
    cudaGetSymbolAddress((void**)&enc, g_enc);
    cudaGetSymbolAddress((void**)&h0, g_h0);
    cudaGetSymbolAddress((void**)&h1, g_h1);

    cudaFuncSetAttribute((const void*)k_main, cudaFuncAttributeMaxDynamicSharedMemorySize,
                         (int)sizeof(Smem));

    bn_zero_kernel<<<1, 32>>>();
    bn_acc_kernel<<<256, 256>>>(in_t);
    bn_fin_kernel<<<1, 32>>>();
    k_main<<<BSZ / 2, NTHR, sizeof(Smem)>>>(P, enc);
    gemm_kernel<true><<<dim3(BSZ / 64, 512 / 64), 256>>>(enc, dec_w0, dec_b0, h0, BSZ, 512, DEC_IN);
    gemm_kernel<true><<<dim3(BSZ / 64, 256 / 64), 256>>>(h0, dec_w1, dec_b1, h1, BSZ, 256, 512);
    final_gemv<<<BSZ / 8, 256>>>(h1, dec_w2, dec_b2, out);
}

// round 15
// speedup vs baseline: 1.1930x; 1.0111x over previous
#include <cuda_runtime.h>
#include <math.h>

#define BSZ 8192
#define SLN 49
#define FDIM 11
#define DEC_IN 138
#define NTHR 256

typedef unsigned long long ull;

__device__ __forceinline__ void fma2(ull& d, ull a, ull b) {
    asm("fma.rn.f32x2 %0, %1, %2, %0;" : "+l"(d) : "l"(a), "l"(b));
}
__device__ __forceinline__ ull pack2(float x, float y) {
    ull u; asm("mov.b64 %0, {%1, %2};" : "=l"(u) : "f"(x), "f"(y)); return u;
}
__device__ __forceinline__ float2 unpack2(ull u) {
    float2 v; asm("mov.b64 {%0, %1}, %2;" : "=f"(v.x), "=f"(v.y) : "l"(u)); return v;
}

// ---------------- device scratch ----------------
__device__ float g_sum[9];
__device__ float g_sumsq[9];
__device__ float g_mean[9];
__device__ float g_rstd[9];
__device__ float g_enc[BSZ * DEC_IN];
__device__ float g_h0[BSZ * 512];
__device__ float g_h1[BSZ * 256];

// ---------------- batch-norm statistics ----------------
__global__ void bn_zero_kernel() {
    if (threadIdx.x < 9) { g_sum[threadIdx.x] = 0.f; g_sumsq[threadIdx.x] = 0.f; }
}

__global__ void bn_acc_kernel(const float* __restrict__ in) {
    float ls[9], lq[9];
#pragma unroll
    for (int f = 0; f < 9; f++) { ls[f] = 0.f; lq[f] = 0.f; }
    int idx0 = blockIdx.x * blockDim.x + threadIdx.x;
    for (int r = idx0; r < BSZ * SLN; r += gridDim.x * blockDim.x) {
        const float* p = in + (size_t)r * FDIM;
#pragma unroll
        for (int f = 0; f < 9; f++) {
            float v = p[f < 8 ? f : 10];
            ls[f] += v; lq[f] += v * v;
        }
    }
#pragma unroll
    for (int f = 0; f < 9; f++) {
#pragma unroll
        for (int o = 16; o; o >>= 1) {
            ls[f] += __shfl_down_sync(0xffffffffu, ls[f], o);
            lq[f] += __shfl_down_sync(0xffffffffu, lq[f], o);
        }
    }
    if ((threadIdx.x & 31) == 0) {
#pragma unroll
        for (int f = 0; f < 9; f++) {
            atomicAdd(&g_sum[f], ls[f]);
            atomicAdd(&g_sumsq[f], lq[f]);
        }
    }
}

__global__ void bn_fin_kernel() {
    int f = threadIdx.x;
    if (f < 9) {
        float n = (float)(BSZ * SLN);
        float mu = g_sum[f] / n;
        float var = g_sumsq[f] / n - mu * mu;
        g_mean[f] = mu;
        g_rstd[f] = rsqrtf(var + 1e-5f);
    }
}

// ---------------- main per-element transformer kernel ----------------
struct MainParams {
    const float *in, *dists, *gamma, *beta;
    const float *xe_w1, *xe_b1, *xe_w2, *xe_b2;
    const float *ye_w1, *ye_b1, *ye_w2, *ye_b2;
    const float *learnable_y, *hidden_tokens;
    const float *Wq, *Wk, *Wv, *Wo, *Wq2, *Wk2, *Wv2, *Wo2;
};

#define TSTR 52
#define KSTR 52
#define SCSTR 52

struct __align__(16) PerElem {
    float in[SLN][12];
    float csT[4][52];
    float snT[4][52];
    float bias[48];
    float ctxT[64][TSTR];
    float KT[64][KSTR];    // roped keys; reused as o-partial scratch after scores
    float V[48][64];
    float H[4][64];
    union {
        float tmpT[64][TSTR];
        struct {
            float sc[32][SCSTR];
            float q[4][64];
            float o[4][64];       // spacer for cross-attn partials
            float k2[4][64];
            float v2[4][64];
            float qc[64];
            float outv[64];
            float a2[32];
        } a;
    } u;
};

struct __align__(16) Smem { PerElem el[2]; };

__global__ void __launch_bounds__(NTHR, 2) k_main(MainParams P, float* __restrict__ enc) {
    extern __shared__ char smem_raw[];
    Smem& s = *reinterpret_cast<Smem*>(smem_raw);
    const int tid = threadIdx.x;
    const int b = blockIdx.x;          // elements 2b, 2b+1
    const int c = tid & 63;
    const int g = tid >> 6;            // group 0..3 (legacy mapping phases)
    const int w = tid >> 5;            // warp 0..7
    const int lane = tid & 31;
    const int ew = w & 1;              // element this warp serves
    const int th = w >> 1;             // t-chunk 0..3 (12 t each)
    const int t0w = th * 12;

    // ---- phase 0 ----
#pragma unroll 1
    for (int e = 0; e < 2; e++) {
        PerElem& E = s.el[e];
        const float* ib = P.in + (size_t)(2 * b + e) * SLN * FDIM;
        for (int idx = tid; idx < SLN * FDIM; idx += NTHR) {
            int t = idx / FDIM, cc = idx % FDIM;
            float v = ib[idx];
            if (cc < 8 || cc == 10) {
                int f = (cc < 8) ? cc : 8;
                v = (v - g_mean[f]) * g_rstd[f] * P.gamma[f] + P.beta[f];
            }
            E.in[t][cc] = v;
        }
        for (int idx = tid; idx < 48; idx += NTHR)
            E.bias[idx] = -P.dists[(size_t)(2 * b + e) * SLN + idx];
        for (int idx = tid; idx < SLN * 4; idx += NTHR) {
            int t = idx >> 2, j = idx & 3;
            float x = ib[t * FDIM + 8], y = ib[t * FDIM + 9];
            float ang = (j == 0) ? 10.f * x : (j == 1) ? 10.f * y : (j == 2) ? x : y;
            E.csT[j][t] = cosf(ang);
            E.snT[j][t] = sinf(ang);
        }
    }
    __syncthreads();

    // ---- x embed stage1 (legacy mapping) ----
    {
        float wv[8];
#pragma unroll
        for (int k = 0; k < 8; k++) wv[k] = __ldg(&P.xe_w1[k * 64 + c]);
        float b1 = P.xe_b1[c];
#pragma unroll
        for (int e = 0; e < 2; e++) {
            PerElem& E = s.el[e];
            for (int t = g; t < SLN; t += 4) {
                float acc = b1;
#pragma unroll
                for (int k = 0; k < 8; k++) acc += E.in[t][k] * wv[k];
                E.u.tmpT[c][t] = acc - tanhf(acc);
            }
        }
    }
    __syncthreads();
    // ---- x embed stage2: warp=(elem,t-chunk), lane handles c=lane & lane+32 ----
    {
        PerElem& E = s.el[ew];
        const float b2v0 = P.xe_b2[lane];
        const float b2v1 = P.xe_b2[lane + 32];
        ull acc[2][6];
#pragma unroll
        for (int p = 0; p < 6; p++) { acc[0][p] = pack2(b2v0, b2v0); acc[1][p] = pack2(b2v1, b2v1); }
        const float* Wc = P.xe_w2 + lane;
#pragma unroll 8
        for (int k = 0; k < 64; k++) {
            float w0 = __ldg(&Wc[k * 64]), w1 = __ldg(&Wc[k * 64 + 32]);
            ull wa = pack2(w0, w0), wb = pack2(w1, w1);
            const ulonglong2* act = reinterpret_cast<const ulonglong2*>(&E.u.tmpT[k][t0w]);
#pragma unroll
            for (int p = 0; p < 3; p++) {
                ulonglong2 a4 = act[p];
                fma2(acc[0][2 * p], a4.x, wa);
                fma2(acc[0][2 * p + 1], a4.y, wa);
                fma2(acc[1][2 * p], a4.x, wb);
                fma2(acc[1][2 * p + 1], a4.y, wb);
            }
        }
#pragma unroll
        for (int half = 0; half < 2; half++) {
            float2 r0 = unpack2(acc[half][0]), r1 = unpack2(acc[half][1]);
            float2 r2 = unpack2(acc[half][2]), r3 = unpack2(acc[half][3]);
            float2 r4 = unpack2(acc[half][4]), r5 = unpack2(acc[half][5]);
            float* dst = &E.ctxT[lane + 32 * half][t0w];
            *reinterpret_cast<float4*>(dst) = make_float4(r0.x, r0.y, r1.x, r1.y);
            *reinterpret_cast<float4*>(dst + 4) = make_float4(r2.x, r2.y, r3.x, r3.y);
            *reinterpret_cast<float4*>(dst + 8) = make_float4(r4.x, r4.y, r5.x, r5.y);
        }
        if (w < 2) {   // tail t=48
            PerElem& Et = s.el[w];
            float a0 = P.xe_b2[lane], a1 = P.xe_b2[lane + 32];
            const float* W = P.xe_w2;
            for (int k = 0; k < 64; k++) {
                float tv = Et.u.tmpT[k][48];
                a0 += tv * __ldg(&W[k * 64 + lane]);
                a1 += tv * __ldg(&W[k * 64 + lane + 32]);
            }
            Et.ctxT[lane][48] = a0;
            Et.ctxT[lane + 32][48] = a1;
        }
    }
    __syncthreads();

    const float scale = 0.35355339059327373f;  // 1/sqrt(8)

#pragma unroll 1
    for (int str = 0; str < 2; ++str) {
        if (str == 1) {
            {
                float w1v = P.ye_w1[c], b1 = P.ye_b1[c];
#pragma unroll
                for (int e = 0; e < 2; e++) {
                    PerElem& E = s.el[e];
                    for (int t = g; t < 48; t += 4) {
                        float acc = E.in[t][10] * w1v + b1;
                        E.u.tmpT[c][t] = acc - tanhf(acc);
                    }
                }
            }
            __syncthreads();
            {
                PerElem& E = s.el[ew];
                const float b2v0 = P.ye_b2[lane];
                const float b2v1 = P.ye_b2[lane + 32];
                ull acc[2][6];
#pragma unroll
                for (int p = 0; p < 6; p++) { acc[0][p] = pack2(b2v0, b2v0); acc[1][p] = pack2(b2v1, b2v1); }
                const float* Wc = P.ye_w2 + lane;
#pragma unroll 8
                for (int k = 0; k < 64; k++) {
                    float w0 = __ldg(&Wc[k * 64]), w1 = __ldg(&Wc[k * 64 + 32]);
                    ull wa = pack2(w0, w0), wb = pack2(w1, w1);
                    const ulonglong2* act = reinterpret_cast<const ulonglong2*>(&E.u.tmpT[k][t0w]);
#pragma unroll
                    for (int p = 0; p < 3; p++) {
                        ulonglong2 a4 = act[p];
                        fma2(acc[0][2 * p], a4.x, wa);
                        fma2(acc[0][2 * p + 1], a4.y, wa);
                        fma2(acc[1][2 * p], a4.x, wb);
                        fma2(acc[1][2 * p + 1], a4.y, wb);
                    }
                }
#pragma unroll
                for (int half = 0; half < 2; half++) {
                    float2 r0 = unpack2(acc[half][0]), r1 = unpack2(acc[half][1]);
                    float2 r2 = unpack2(acc[half][2]), r3 = unpack2(acc[half][3]);
                    float2 r4 = unpack2(acc[half][4]), r5 = unpack2(acc[half][5]);
                    float* dst = &E.ctxT[lane + 32 * half][t0w];
                    *reinterpret_cast<float4*>(dst) = make_float4(r0.x, r0.y, r1.x, r1.y);
                    *reinterpret_cast<float4*>(dst + 4) = make_float4(r2.x, r2.y, r3.x, r3.y);
                    *reinterpret_cast<float4*>(dst + 8) = make_float4(r4.x, r4.y, r5.x, r5.y);
                }
                if (w < 2) {
                    s.el[w].ctxT[lane][48] = P.learnable_y[lane];
                    s.el[w].ctxT[lane + 32][48] = P.learnable_y[lane + 32];
                }
            }
            __syncthreads();
        }

#pragma unroll
        for (int e = 0; e < 2; e++) s.el[e].H[g][c] = P.hidden_tokens[g * 64 + c];
        __syncthreads();

#pragma unroll 1
        for (int l = 0; l < 2; ++l) {
            const int woff = (l * 2 + str) * 4096;
            // ---- phase A: K+V projection, warp=(elem,t-chunk), lane = c & c+32, fused rope ----
            {
                PerElem& E = s.el[ew];
                ull accK[2][6], accV[2][6];
#pragma unroll
                for (int p = 0; p < 6; p++) {
                    accK[0][p] = 0ull; accK[1][p] = 0ull;
                    accV[0][p] = 0ull; accV[1][p] = 0ull;
                }
                const float* WkB = P.Wk + woff + lane;
                const float* WvB = P.Wv + woff + lane;
#pragma unroll 8
                for (int k = 0; k < 64; k++) {
                    float wk0 = __ldg(&WkB[k * 64]), wk1 = __ldg(&WkB[k * 64 + 32]);
                    float wv0 = __ldg(&WvB[k * 64]), wv1 = __ldg(&WvB[k * 64 + 32]);
                    ull wka = pack2(wk0, wk0), wkb = pack2(wk1, wk1);
                    ull wva = pack2(wv0, wv0), wvb = pack2(wv1, wv1);
                    const ulonglong2* act = reinterpret_cast<const ulonglong2*>(&E.ctxT[k][t0w]);
#pragma unroll
                    for (int p = 0; p < 3; p++) {
                        ulonglong2 a4 = act[p];
                        fma2(accK[0][2 * p], a4.x, wka);
                        fma2(accK[0][2 * p + 1], a4.y, wka);
                        fma2(accK[1][2 * p], a4.x, wkb);
                        fma2(accK[1][2 * p + 1], a4.y, wkb);
                        fma2(accV[0][2 * p], a4.x, wva);
                        fma2(accV[0][2 * p + 1], a4.y, wva);
                        fma2(accV[1][2 * p], a4.x, wvb);
                        fma2(accV[1][2 * p + 1], a4.y, wvb);
                    }
                }
                // V stores
#pragma unroll
                for (int half = 0; half < 2; half++)
#pragma unroll
                    for (int p = 0; p < 6; p++) {
                        float2 vv = unpack2(accV[half][p]);
                        E.V[t0w + 2 * p][lane + 32 * half] = vv.x;
                        E.V[t0w + 2 * p + 1][lane + 32 * half] = vv.y;
                    }
                // fused rope: partner lane = lane^1
                {
                    const int j = (lane >> 1) & 3;
                    const float sgn = (lane & 1) ? 1.f : -1.f;
                    float4 csA = *reinterpret_cast<const float4*>(&E.csT[j][t0w]);
                    float4 csB = *reinterpret_cast<const float4*>(&E.csT[j][t0w + 4]);
                    float4 csC = *reinterpret_cast<const float4*>(&E.csT[j][t0w + 8]);
                    float4 snA = *reinterpret_cast<const float4*>(&E.snT[j][t0w]);
                    float4 snB = *reinterpret_cast<const float4*>(&E.snT[j][t0w + 4]);
                    float4 snC = *reinterpret_cast<const float4*>(&E.snT[j][t0w + 8]);
                    ull cs2[6] = {pack2(csA.x, csA.y), pack2(csA.z, csA.w),
                                  pack2(csB.x, csB.y), pack2(csB.z, csB.w),
                                  pack2(csC.x, csC.y), pack2(csC.z, csC.w)};
                    ull sn2[6] = {pack2(sgn * snA.x, sgn * snA.y), pack2(sgn * snA.z, sgn * snA.w),
                                  pack2(sgn * snB.x, sgn * snB.y), pack2(sgn * snB.z, sgn * snB.w),
                                  pack2(sgn * snC.x, sgn * snC.y), pack2(sgn * snC.z, sgn * snC.w)};
#pragma unroll
                    for (int half = 0; half < 2; half++) {
                        float2 rr[6];
#pragma unroll
                        for (int p = 0; p < 6; p++) {
                            float2 mv = unpack2(accK[half][p]);
                            float ox = __shfl_xor_sync(0xffffffffu, mv.x, 1);
                            float oy = __shfl_xor_sync(0xffffffffu, mv.y, 1);
                            ull r = 0ull;
                            fma2(r, accK[half][p], cs2[p]);
                            fma2(r, pack2(ox, oy), sn2[p]);
                            rr[p] = unpack2(r);
                        }
                        float* dst = &E.KT[lane + 32 * half][t0w];
                        *reinterpret_cast<float4*>(dst) = make_float4(rr[0].x, rr[0].y, rr[1].x, rr[1].y);
                        *reinterpret_cast<float4*>(dst + 4) = make_float4(rr[2].x, rr[2].y, rr[3].x, rr[3].y);
                        *reinterpret_cast<float4*>(dst + 8) = make_float4(rr[4].x, rr[4].y, rr[5].x, rr[5].y);
                    }
                }
            }
            // q projection (legacy mapping, row = g)
            {
                float acc[2] = {0.f, 0.f};
#pragma unroll
                for (int kc = 0; kc < 64; kc += 8) {
                    float wv[8];
#pragma unroll
                    for (int j = 0; j < 8; j++) wv[j] = __ldg(&P.Wq[woff + (kc + j) * 64 + c]);
#pragma unroll
                    for (int e = 0; e < 2; e++) {
                        const float4* h4 = reinterpret_cast<const float4*>(&s.el[e].H[g][kc]);
#pragma unroll
                        for (int q4 = 0; q4 < 2; q4++) {
                            float4 hv = h4[q4];
                            acc[e] += hv.x * wv[4 * q4] + hv.y * wv[4 * q4 + 1] + hv.z * wv[4 * q4 + 2] + hv.w * wv[4 * q4 + 3];
                        }
                    }
                }
                s.el[0].u.a.q[g][c] = acc[0];
                s.el[1].u.a.q[g][c] = acc[1];
            }
            __syncthreads();
            // ---- phase B: fused scores + softmax (q preloaded as float4) ----
            {
                int r = tid >> 3, l8 = tid & 7;
                int h = r >> 2, i = r & 3;
                int t0 = l8 * 6;
                float q0[2][8];
#pragma unroll
                for (int e = 0; e < 2; e++) {
                    float4 qa = *reinterpret_cast<const float4*>(&s.el[e].u.a.q[i][h * 8]);
                    float4 qb = *reinterpret_cast<const float4*>(&s.el[e].u.a.q[i][h * 8 + 4]);
                    q0[e][0] = qa.x; q0[e][1] = qa.y; q0[e][2] = qa.z; q0[e][3] = qa.w;
                    q0[e][4] = qb.x; q0[e][5] = qb.y; q0[e][6] = qb.z; q0[e][7] = qb.w;
                }
                ull acc[2][3] = {{0ull, 0ull, 0ull}, {0ull, 0ull, 0ull}};
#pragma unroll
                for (int d = 0; d < 8; d++) {
#pragma unroll
                    for (int e = 0; e < 2; e++) {
                        PerElem& E = s.el[e];
                        ull q2 = pack2(q0[e][d], q0[e][d]);
                        const float2* kt = reinterpret_cast<const float2*>(&E.KT[h * 8 + d][t0]);
#pragma unroll
                        for (int p = 0; p < 3; p++) {
                            float2 kv = kt[p];
                            fma2(acc[e][p], pack2(kv.x, kv.y), q2);
                        }
                    }
                }
#pragma unroll
                for (int e = 0; e < 2; e++) {
                    PerElem& E = s.el[e];
                    float sc[6];
#pragma unroll
                    for (int p = 0; p < 3; p++) {
                        float2 v = unpack2(acc[e][p]);
                        float2 bb = *reinterpret_cast<const float2*>(&E.bias[t0 + 2 * p]);
                        sc[2 * p] = v.x * scale + bb.x;
                        sc[2 * p + 1] = v.y * scale + bb.y;
                    }
                    float m = sc[0];
#pragma unroll
                    for (int ee = 1; ee < 6; ee++) m = fmaxf(m, sc[ee]);
#pragma unroll
                    for (int o = 1; o < 8; o <<= 1) m = fmaxf(m, __shfl_xor_sync(0xffffffffu, m, o, 8));
                    float sum = 0.f;
#pragma unroll
                    for (int ee = 0; ee < 6; ee++) { sc[ee] = __expf(sc[ee] - m); sum += sc[ee]; }
#pragma unroll
                    for (int o = 1; o < 8; o <<= 1) sum += __shfl_xor_sync(0xffffffffu, sum, o, 8);
                    float inv = 1.f / sum;
#pragma unroll
                    for (int p = 0; p < 3; p++)
                        *reinterpret_cast<float2*>(&E.u.a.sc[r][t0 + 2 * p]) =
                            make_float2(sc[2 * p] * inv, sc[2 * p + 1] * inv);
                }
            }
            __syncthreads();
            // ---- phase C: o = a @ V partials into KT scratch ----
            {
                int p = tid & 31, g2 = tid >> 5;
                int gg = g2 & 3, thh = g2 >> 2;
                int r = (p >> 2) * 4 + gg;
                int tb = thh * 24;
                ull acc[2] = {0ull, 0ull};
#pragma unroll
                for (int q = 0; q < 6; q++) {
                    float4 av0 = reinterpret_cast<const float4*>(&s.el[0].u.a.sc[r][tb])[q];
                    float4 av1 = reinterpret_cast<const float4*>(&s.el[1].u.a.sc[r][tb])[q];
                    float a0[4] = {av0.x, av0.y, av0.z, av0.w};
                    float a1[4] = {av1.x, av1.y, av1.z, av1.w};
#pragma unroll
                    for (int cmp = 0; cmp < 4; cmp++) {
                        int t = tb + q * 4 + cmp;
                        float2 v0 = *reinterpret_cast<const float2*>(&s.el[0].V[t][2 * p]);
                        float2 v1 = *reinterpret_cast<const float2*>(&s.el[1].V[t][2 * p]);
                        fma2(acc[0], pack2(v0.x, v0.y), pack2(a0[cmp], a0[cmp]));
                        fma2(acc[1], pack2(v1.x, v1.y), pack2(a1[cmp], a1[cmp]));
                    }
                }
                float* ob0 = &s.el[0].KT[0][0];
                float* ob1 = &s.el[1].KT[0][0];
                *reinterpret_cast<float2*>(&ob0[thh * 256 + gg * 64 + 2 * p]) = unpack2(acc[0]);
                *reinterpret_cast<float2*>(&ob1[thh * 256 + gg * 64 + 2 * p]) = unpack2(acc[1]);
            }
            __syncthreads();
            // ---- phase D: H += (partial0+partial1) @ Wo ----
            {
                float acc[2] = {0.f, 0.f};
#pragma unroll
                for (int kc = 0; kc < 64; kc += 8) {
                    float wv[8];
#pragma unroll
                    for (int j = 0; j < 8; j++) wv[j] = __ldg(&P.Wo[woff + (kc + j) * 64 + c]);
#pragma unroll
                    for (int e = 0; e < 2; e++) {
                        const float* ob = &s.el[e].KT[0][0];
#pragma unroll
                        for (int q4 = 0; q4 < 2; q4++) {
                            float4 oa = *reinterpret_cast<const float4*>(&ob[g * 64 + kc + 4 * q4]);
                            float4 obp = *reinterpret_cast<const float4*>(&ob[256 + g * 64 + kc + 4 * q4]);
                            float ov0 = oa.x + obp.x, ov1 = oa.y + obp.y;
                            float ov2 = oa.z + obp.z, ov3 = oa.w + obp.w;
                            acc[e] += ov0 * wv[4 * q4] + ov1 * wv[4 * q4 + 1] + ov2 * wv[4 * q4 + 2] + ov3 * wv[4 * q4 + 3];
                        }
                    }
                }
                s.el[0].H[g][c] += acc[0];
                s.el[1].H[g][c] += acc[1];
            }
            __syncthreads();
        }

        // ---- cross attention ----
        {
            const float* Wk2B = P.Wk2 + str * 4096 + c;
            const float* Wv2B = P.Wv2 + str * 4096 + c;
            float pk[2][4] = {}, pv[2][4] = {};
            const int k0 = g * 16;
            for (int kk = k0; kk < k0 + 16; kk += 2) {
                float wkA = __ldg(&Wk2B[kk * 64]), wkB_ = __ldg(&Wk2B[(kk + 1) * 64]);
                float wvA = __ldg(&Wv2B[kk * 64]), wvB_ = __ldg(&Wv2B[(kk + 1) * 64]);
#pragma unroll
                for (int e = 0; e < 2; e++)
#pragma unroll
                    for (int i = 0; i < 4; i++) {
                        float2 hv = *reinterpret_cast<const float2*>(&s.el[e].H[i][kk]);
                        pk[e][i] += hv.x * wkA + hv.y * wkB_;
                        pv[e][i] += hv.x * wvA + hv.y * wvB_;
                    }
            }
#pragma unroll
            for (int e = 0; e < 2; e++) {
                float* part = &s.el[e].u.a.sc[0][0];
#pragma unroll
                for (int i = 0; i < 4; i++) {
                    part[g * 256 + i * 64 + c] = pk[e][i];
                    part[1024 + g * 256 + i * 64 + c] = pv[e][i];
                }
            }
        }
        __syncthreads();
        {
#pragma unroll
            for (int e = 0; e < 2; e++) {
                const float* part = &s.el[e].u.a.sc[0][0];
                float k2v = part[g * 64 + c] + part[256 + g * 64 + c] + part[512 + g * 64 + c] + part[768 + g * 64 + c];
                float v2v = part[1024 + g * 64 + c] + part[1280 + g * 64 + c] + part[1536 + g * 64 + c] + part[1792 + g * 64 + c];
                s.el[e].u.a.k2[g][c] = k2v;
                s.el[e].u.a.v2[g][c] = v2v;
            }
            if (tid < 128) {
                int e = tid >> 6, q = tid & 63;
                PerElem& E = s.el[e];
                float acc = 0.f;
                const float* W = P.Wq2 + str * 4096 + q;
#pragma unroll 8
                for (int k = 0; k < 64; k++) acc += E.ctxT[k][48] * __ldg(&W[k * 64]);
                float other = __shfl_xor_sync(0xffffffffu, acc, 1);
                int jj = (q >> 1) & 3;
                float csv = E.csT[jj][48], snv = E.snT[jj][48];
                E.u.a.qc[q] = (q & 1) ? (snv * other + csv * acc) : (csv * acc - snv * other);
            }
        }
        __syncthreads();
        if (tid < 16) {
            int e = tid >> 3, h = tid & 7;
            PerElem& E = s.el[e];
            float scv[4], m = -1e30f;
#pragma unroll
            for (int i = 0; i < 4; i++) {
                float acc = 0.f;
#pragma unroll
                for (int dd = 0; dd < 8; dd++) acc += E.u.a.qc[h * 8 + dd] * E.u.a.k2[i][h * 8 + dd];
                scv[i] = acc * scale;
                m = fmaxf(m, scv[i]);
            }
            float sum = 0.f;
#pragma unroll
            for (int i = 0; i < 4; i++) { scv[i] = __expf(scv[i] - m); sum += scv[i]; }
            float inv = 1.f / sum;
#pragma unroll
            for (int i = 0; i < 4; i++) E.u.a.a2[h * 4 + i] = scv[i] * inv;
        }
        __syncthreads();
        if (tid < 128) {
            int e = tid >> 6, q = tid & 63;
            PerElem& E = s.el[e];
            int h = q >> 3;
            float acc = 0.f;
#pragma unroll
            for (int i = 0; i < 4; i++) acc += E.u.a.a2[h * 4 + i] * E.u.a.v2[i][q];
            E.u.a.outv[q] = acc;
        }
        __syncthreads();
        if (tid < 128) {
            int e = tid >> 6, q = tid & 63;
            PerElem& E = s.el[e];
            float acc = 0.f;
            const float* W = P.Wo2 + str * 4096 + q;
#pragma unroll 8
            for (int k = 0; k < 64; k++) acc += E.u.a.outv[k] * __ldg(&W[k * 64]);
            enc[(size_t)(2 * b + e) * DEC_IN + str * 64 + q] = acc;
        }
        __syncthreads();
    }

    if (tid < 10) {
        enc[(size_t)(2 * b) * DEC_IN + 128 + tid] = s.el[0].in[48][tid];
        enc[(size_t)(2 * b + 1) * DEC_IN + 128 + tid] = s.el[1].in[48][tid];
    }
}

// ---------------- decoder GEMMs: 128x64 tile, 8x4 per thread, f32x2 ----------------
template <bool ACT>
__global__ void __launch_bounds__(256) gemm_kernel(const float* __restrict__ A, const float* __restrict__ B,
                                                   const float* __restrict__ bias, float* __restrict__ C,
                                                   int M, int N, int K) {
    const int BK = 16;
    __shared__ float As[BK][132];   // 128 rows + pad
    __shared__ float Bs[BK][64];
    int tx = threadIdx.x & 15;      // 16 col-groups of 4
    int ty = threadIdx.x >> 4;      // 16 row-groups of 8
    int bm = blockIdx.x * 128, bn = blockIdx.y * 64;
    ull acc2[8][2] = {};
    for (int k0 = 0; k0 < K; k0 += BK) {
        for (int idx = threadIdx.x; idx < 128 * BK; idx += 256) {
            int r = idx >> 4, kk = idx & 15;
            As[kk][r] = (k0 + kk < K) ? A[(size_t)(bm + r) * K + k0 + kk] : 0.f;
        }
        for (int idx = threadIdx.x; idx < BK * 64; idx += 256) {
            int kk = idx >> 6, cc = idx & 63;
            Bs[kk][cc] = (k0 + kk < K) ? B[(size_t)(k0 + kk) * N + bn + cc] : 0.f;
        }
        __syncthreads();
#pragma unroll
        for (int kk = 0; kk < BK; kk++) {
            float4 a0 = *(const float4*)&As[kk][ty * 8];
            float4 a1 = *(const float4*)&As[kk][ty * 8 + 4];
            float4 bv = *(const float4*)&Bs[kk][tx * 4];
            ull b01 = pack2(bv.x, bv.y), b23 = pack2(bv.z, bv.w);
            float a[8] = {a0.x, a0.y, a0.z, a0.w, a1.x, a1.y, a1.z, a1.w};
#pragma unroll
            for (int i = 0; i < 8; i++) {
                ull a2 = pack2(a[i], a[i]);
                fma2(acc2[i][0], b01, a2);
                fma2(acc2[i][1], b23, a2);
            }
        }
        __syncthreads();
    }
#pragma unroll
    for (int i = 0; i < 8; i++) {
        int r = bm + ty * 8 + i;
        float2 v01 = unpack2(acc2[i][0]);
        float2 v23 = unpack2(acc2[i][1]);
        float vals[4] = {v01.x, v01.y, v23.x, v23.y};
#pragma unroll
        for (int j = 0; j < 4; j++) {
            int cc = bn + tx * 4 + j;
            float v = vals[j] + bias[cc];
            if (ACT) v -= tanhf(v);
            C[(size_t)r * N + cc] = v;
        }
    }
}

__global__ void __launch_bounds__(256) final_gemv(const float* __restrict__ H1, const float* __restrict__ w,
                                                  const float* __restrict__ b2, float* __restrict__ out) {
    int b = blockIdx.x * 8 + (threadIdx.x >> 5);
    int lane = threadIdx.x & 31;
    const float* row = H1 + (size_t)b * 256;
    float acc = 0.f;
#pragma unroll
    for (int k = lane; k < 256; k += 32) acc += row[k] * w[k];
#pragma unroll
    for (int o = 16; o; o >>= 1) acc += __shfl_down_sync(0xffffffffu, acc, o);
    if (lane == 0) out[b] = acc + b2[0];
}

// ---------------- launch ----------------
extern "C" void kernel_launch(void* const* d_in, const int* in_sizes, int n_in,
                              void* d_out, int out_size) {
    const float* in_t = (const float*)d_in[0];
    MainParams P;
    P.in = in_t;
    P.dists = (const float*)d_in[1];
    P.gamma = (const float*)d_in[3];  P.beta = (const float*)d_in[4];
    P.xe_w1 = (const float*)d_in[5];  P.xe_b1 = (const float*)d_in[6];
    P.xe_w2 = (const float*)d_in[7];  P.xe_b2 = (const float*)d_in[8];
    P.ye_w1 = (const float*)d_in[9];  P.ye_b1 = (const float*)d_in[10];
    P.ye_w2 = (const float*)d_in[11]; P.ye_b2 = (const float*)d_in[12];
    P.learnable_y = (const float*)d_in[13];
    P.hidden_tokens = (const float*)d_in[14];
    P.Wq = (const float*)d_in[15]; P.Wk = (const float*)d_in[16];
    P.Wv = (const float*)d_in[17]; P.Wo = (const float*)d_in[18];
    P.Wq2 = (const float*)d_in[19]; P.Wk2 = (const float*)d_in[20];
    P.Wv2 = (const float*)d_in[21]; P.Wo2 = (const float*)d_in[22];
    const float* dec_w0 = (const float*)d_in[23];
    const float* dec_b0 = (const float*)d_in[24];
    const float* dec_w1 = (const float*)d_in[25];
    const float* dec_b1 = (const float*)d_in[26];
    const float* dec_w2 = (const float*)d_in[27];
    const float* dec_b2 = (const float*)d_in[28];
    float* out = (float*)d_out;

    float *enc, *h0, *h1;
    cudaGetSymbolAddress((void**)&enc, g_enc);
    cudaGetSymbolAddress((void**)&h0, g_h0);
    cudaGetSymbolAddress((void**)&h1, g_h1);

    cudaFuncSetAttribute((const void*)k_main, cudaFuncAttributeMaxDynamicSharedMemorySize,
                         (int)sizeof(Smem));

    bn_zero_kernel<<<1, 32>>>();
    bn_acc_kernel<<<256, 256>>>(in_t);
    bn_fin_kernel<<<1, 32>>>();
    k_main<<<BSZ / 2, NTHR, sizeof(Smem)>>>(P, enc);
    gemm_kernel<true><<<dim3(BSZ / 128, 512 / 64), 256>>>(enc, dec_w0, dec_b0, h0, BSZ, 512, DEC_IN);
    gemm_kernel<true><<<dim3(BSZ / 128, 256 / 64), 256>>>(h0, dec_w1, dec_b1, h1, BSZ, 256, 512);
    final_gemv<<<BSZ / 8, 256>>>(h1, dec_w2, dec_b2, out);
}